// round 13
// baseline (speedup 1.0000x reference)
#include <cuda_runtime.h>
#include <cuda_bf16.h>
#include <stdint.h>
#include <math.h>

#define NROWS 131072
#define DIMD  512
#define HID   1024
#define NMEM  512

// ---------------- scratch ----------------
__device__ __nv_bfloat16 g_h   [(size_t)NROWS * HID];
__device__ __nv_bfloat16 g_x0b [(size_t)NROWS * DIMD];  // hi(x0)
__device__ __nv_bfloat16 g_x0lo[(size_t)NROWS * DIMD];  // lo(x0)
__device__ __nv_bfloat16 g_x1b [(size_t)NROWS * DIMD];  // hi(x1)
__device__ __nv_bfloat16 g_x1lo[(size_t)NROWS * DIMD];  // lo(x1)
__device__ __nv_bfloat16 g_wub[(size_t)HID * DIMD];     // [n][k]
__device__ __nv_bfloat16 g_wdb[(size_t)DIMD * HID];     // [n][k]
__device__ __nv_bfloat16 g_mbb[(size_t)NMEM * DIMD];    // [code][k]
__device__ float         g_cnorm[NMEM];

// ---------------- helpers ----------------
static __device__ __forceinline__ uint32_t smem_u32(const void* p) {
    uint32_t a;
    asm("{ .reg .u64 t; cvta.to.shared.u64 t, %1; cvt.u32.u64 %0, t; }" : "=r"(a) : "l"(p));
    return a;
}
static __device__ __forceinline__ uint32_t f2bf2(float lo, float hi) {
    uint32_t r;
    asm("cvt.rn.bf16x2.f32 %0, %1, %2;" : "=r"(r) : "f"(hi), "f"(lo));
    return r;
}
static __device__ __forceinline__ void cp16(uint32_t saddr, const void* g) {
    asm volatile("cp.async.cg.shared.global [%0], [%1], 16;" :: "r"(saddr), "l"(g));
}
#define CP_COMMIT() asm volatile("cp.async.commit_group;" ::: "memory")
#define CP_WAIT(n)  asm volatile("cp.async.wait_group %0;" :: "n"(n) : "memory")

// streaming (evict-first) loads/stores for single-use data
static __device__ __forceinline__ float4 ldcs4f(const float* p) {
    float4 v;
    asm volatile("ld.global.cs.v4.f32 {%0,%1,%2,%3}, [%4];"
        : "=f"(v.x), "=f"(v.y), "=f"(v.z), "=f"(v.w) : "l"(p));
    return v;
}
static __device__ __forceinline__ uint2 ldcs2u(const void* p) {
    uint2 v;
    asm volatile("ld.global.cs.v2.b32 {%0,%1}, [%2];" : "=r"(v.x), "=r"(v.y) : "l"(p));
    return v;
}
static __device__ __forceinline__ void stcs4u(void* p, uint4 v) {
    asm volatile("st.global.cs.v4.b32 [%0], {%1,%2,%3,%4};"
        :: "l"(p), "r"(v.x), "r"(v.y), "r"(v.z), "r"(v.w));
}
static __device__ __forceinline__ void stcs2u(void* p, uint2 v) {
    asm volatile("st.global.cs.v2.b32 [%0], {%1,%2};" :: "l"(p), "r"(v.x), "r"(v.y));
}
static __device__ __forceinline__ void stcs4f(float* p, float4 v) {
    asm volatile("st.global.cs.v4.f32 [%0], {%1,%2,%3,%4};"
        :: "l"(p), "f"(v.x), "f"(v.y), "f"(v.z), "f"(v.w));
}

static __device__ __forceinline__ void ldsm4(uint32_t* a, uint32_t addr) {
    asm volatile("ldmatrix.sync.aligned.m8n8.x4.shared.b16 {%0,%1,%2,%3}, [%4];"
        : "=r"(a[0]), "=r"(a[1]), "=r"(a[2]), "=r"(a[3]) : "r"(addr));
}
static __device__ __forceinline__ void mma16816(float* c, const uint32_t* a, const uint32_t* b) {
    asm volatile("mma.sync.aligned.m16n8k16.row.col.f32.bf16.bf16.f32 "
        "{%0,%1,%2,%3}, {%4,%5,%6,%7}, {%8,%9}, {%0,%1,%2,%3};"
        : "+f"(c[0]), "+f"(c[1]), "+f"(c[2]), "+f"(c[3])
        : "r"(a[0]), "r"(a[1]), "r"(a[2]), "r"(a[3]), "r"(b[0]), "r"(b[1]));
}
static __device__ __forceinline__ float fixv(float x) {
    if (isnan(x)) return 0.f;
    if (isinf(x)) return x > 0.f ? 1.f : -1.f;
    return x;
}
static __device__ __forceinline__ void hilo(float v, __nv_bfloat16& h, __nv_bfloat16& l) {
    h = __float2bfloat16(v);
    l = __float2bfloat16(v - __bfloat162float(h));
}

// 32x64 warp tile, NKS*16 k per call. A stride astride elems (k-contig rows);
// B tile rows (n-major) stride 72 elems. c[2][8][4]. Warp (wm 0..3, wn 0..1).
template<int NKS>
static __device__ __forceinline__ void compute32x64(
    float c[2][8][4], uint32_t sAu, uint32_t sBu, int astride,
    int kbase, int wm, int wn, int lane)
{
    const int al = lane & 15, ah = (lane >> 4) << 3;
    const int bn = (lane & 7) + ((lane >> 4) << 3);
    const int bk = ((lane >> 3) & 1) << 3;
    #pragma unroll
    for (int ks = 0; ks < NKS; ks++) {
        const int koff = kbase + ks * 16;
        uint32_t a[2][4], bf[4][4];
        #pragma unroll
        for (int mi = 0; mi < 2; mi++) {
            uint32_t arow = (uint32_t)(wm * 32 + mi * 16 + al);
            ldsm4(a[mi], sAu + (arow * astride + koff + ah) * 2u);
        }
        #pragma unroll
        for (int p = 0; p < 4; p++) {
            uint32_t brow = (uint32_t)(wn * 64 + p * 16 + bn);
            ldsm4(bf[p], sBu + (brow * 72u + ks * 16 + bk) * 2u);
        }
        #pragma unroll
        for (int mi = 0; mi < 2; mi++)
            #pragma unroll
            for (int p = 0; p < 4; p++) {
                mma16816(c[mi][p * 2],     a[mi], &bf[p][0]);
                mma16816(c[mi][p * 2 + 1], a[mi], &bf[p][2]);
            }
    }
}

// ---------------- prep + combine (single launch) ----------------
__global__ void __launch_bounds__(256) kpre(const float* __restrict__ ie,
                                            const float* __restrict__ nb,
                                            const float* __restrict__ mu,
                                            const float* __restrict__ wu,
                                            const float* __restrict__ wd,
                                            const float* __restrict__ mb)
{
    int b = blockIdx.x;
    if (b < 32768) {
        size_t base = ((size_t)b * 256 + threadIdx.x) * 8;
        int kcol = (int)(base & (DIMD - 1));
        float4 e0 = ldcs4f(ie + base);
        float4 e1 = ldcs4f(ie + base + 4);
        float4 n0 = ldcs4f(nb + base);
        float4 n1 = ldcs4f(nb + base + 4);
        float4 m0 = *(const float4*)(mu + kcol);
        float4 m1 = *(const float4*)(mu + kcol + 4);
        float v[8];
        v[0] = e0.x + 0.1f * n0.x + m0.x;
        v[1] = e0.y + 0.1f * n0.y + m0.y;
        v[2] = e0.z + 0.1f * n0.z + m0.z;
        v[3] = e0.w + 0.1f * n0.w + m0.w;
        v[4] = e1.x + 0.1f * n1.x + m1.x;
        v[5] = e1.y + 0.1f * n1.y + m1.y;
        v[6] = e1.z + 0.1f * n1.z + m1.z;
        v[7] = e1.w + 0.1f * n1.w + m1.w;
        __nv_bfloat16 h[8], l[8];
        #pragma unroll
        for (int i = 0; i < 8; i++) hilo(v[i], h[i], l[i]);
        stcs4u(g_x0b  + base, *(uint4*)h);
        stcs4u(g_x0lo + base, *(uint4*)l);
    } else if (b < 34816) {
        int i = (b - 32768) * 256 + threadIdx.x;
        int n = i >> 9, k = i & 511;
        g_wub[i] = __float2bfloat16(wu[(size_t)k * HID + n]);
    } else if (b < 36864) {
        int i = (b - 34816) * 256 + threadIdx.x;
        int n = i >> 10, k = i & 1023;
        g_wdb[i] = __float2bfloat16(wd[(size_t)k * DIMD + n]);
    } else if (b < 37888) {
        int i = (b - 36864) * 256 + threadIdx.x;
        g_mbb[i] = __float2bfloat16(mb[i]);
    } else {
        int code = (b - 37888) * 8 + (threadIdx.x >> 5);
        int lane = threadIdx.x & 31;
        float s = 0.f;
        #pragma unroll
        for (int t = 0; t < 16; t++) {
            float v = mb[(size_t)code * DIMD + t * 32 + lane];
            s += v * v;
        }
        #pragma unroll
        for (int o = 16; o > 0; o >>= 1) s += __shfl_xor_sync(0xffffffffu, s, o);
        if (lane == 0) g_cnorm[code] = s;
    }
}

// BK=64 tiles: 128x72 bf16 = 18432 B per operand; 3 stages of (A|B).
#define HTILE_B 18432
#define STAGE_B (2 * HTILE_B)
#define G12_DS  (3 * STAGE_B)      // 110592
#define G3_DS   G12_DS

// ================= G1: h = silu(x0b @ Wu^T + bu) =================
__global__ void __launch_bounds__(256, 2) g1_kernel(const float* __restrict__ bu)
{
    extern __shared__ char dyn[];
    const uint32_t sbase = smem_u32(dyn);
    const int tid = threadIdx.x, lane = tid & 31, wid = tid >> 5;
    const int wm = wid & 3, wn = wid >> 2;
    const int m0 = blockIdx.y << 7, n0 = blockIdx.x << 7;

    float c[2][8][4];
    #pragma unroll
    for (int i = 0; i < 2; i++)
        #pragma unroll
        for (int j = 0; j < 8; j++)
            #pragma unroll
            for (int q = 0; q < 4; q++) c[i][j][q] = 0.f;

    const int rr = tid >> 3, ch = tid & 7;
    auto issue = [&](int stage, int k0) {
        uint32_t sa = sbase + stage * STAGE_B;
        uint32_t sb = sa + HTILE_B;
        #pragma unroll
        for (int u = 0; u < 4; u++) {
            int r = rr + u * 32;
            cp16(sa + (uint32_t)(r * 144 + ch * 16), &g_x0b[(size_t)(m0 + r) * DIMD + k0 + ch * 8]);
            cp16(sb + (uint32_t)(r * 144 + ch * 16), &g_wub[(size_t)(n0 + r) * DIMD + k0 + ch * 8]);
        }
    };
    issue(0, 0);  CP_COMMIT();
    issue(1, 64); CP_COMMIT();

    const int NK = DIMD / 64;  // 8
    for (int ko = 0; ko < NK; ko++) {
        CP_WAIT(1);
        __syncthreads();
        if (ko + 2 < NK) issue((ko + 2) % 3, (ko + 2) * 64);
        CP_COMMIT();
        uint32_t sa = sbase + (uint32_t)(ko % 3) * STAGE_B;
        compute32x64<4>(c, sa, sa + HTILE_B, 72, 0, wm, wn, lane);
    }
    CP_WAIT(0);
    __syncthreads();

    // stage h tile bf16 (stride 136 -> 272B rows, 16B-aligned), coalesced cs copy out
    __nv_bfloat16* sEp = (__nv_bfloat16*)dyn;
    const int g = lane >> 2, t4 = lane & 3;
    #pragma unroll
    for (int mi = 0; mi < 2; mi++) {
        int r0 = wm * 32 + mi * 16 + g;
        #pragma unroll
        for (int nj = 0; nj < 8; nj++) {
            int cc = wn * 64 + nj * 8 + t4 * 2;
            float2 b2 = *(const float2*)&bu[n0 + cc];
            float v0 = c[mi][nj][0] + b2.x;
            float v1 = c[mi][nj][1] + b2.y;
            float v2 = c[mi][nj][2] + b2.x;
            float v3 = c[mi][nj][3] + b2.y;
            v0 = v0 / (1.f + __expf(-v0));
            v1 = v1 / (1.f + __expf(-v1));
            v2 = v2 / (1.f + __expf(-v2));
            v3 = v3 / (1.f + __expf(-v3));
            *(uint32_t*)&sEp[r0 * 136 + cc]       = f2bf2(v0, v1);
            *(uint32_t*)&sEp[(r0 + 8) * 136 + cc] = f2bf2(v2, v3);
        }
    }
    __syncthreads();
    #pragma unroll
    for (int u = 0; u < 8; u++) {
        int idx = u * 256 + tid, r = idx >> 4, cc = (idx & 15) * 8;
        stcs4u(&g_h[(size_t)(m0 + r) * HID + n0 + cc], *(uint4*)&sEp[r * 136 + cc]);
    }
}

// ================= G2: x1 = x0 + tanh(gate) * (h @ Wd^T + bd), hi/lo out =================
__global__ void __launch_bounds__(256, 2) g2_kernel(const float* __restrict__ bd,
                                                    const float* __restrict__ gate)
{
    extern __shared__ char dyn[];
    const uint32_t sbase = smem_u32(dyn);
    const int tid = threadIdx.x, lane = tid & 31, wid = tid >> 5;
    const int wm = wid & 3, wn = wid >> 2;
    const int m0 = blockIdx.y << 7, n0 = blockIdx.x << 7;

    float c[2][8][4];
    #pragma unroll
    for (int i = 0; i < 2; i++)
        #pragma unroll
        for (int j = 0; j < 8; j++)
            #pragma unroll
            for (int q = 0; q < 4; q++) c[i][j][q] = 0.f;

    const int rr = tid >> 3, ch = tid & 7;
    auto issue = [&](int stage, int k0) {
        uint32_t sa = sbase + stage * STAGE_B;
        uint32_t sb = sa + HTILE_B;
        #pragma unroll
        for (int u = 0; u < 4; u++) {
            int r = rr + u * 32;
            cp16(sa + (uint32_t)(r * 144 + ch * 16), &g_h[(size_t)(m0 + r) * HID + k0 + ch * 8]);
            cp16(sb + (uint32_t)(r * 144 + ch * 16), &g_wdb[(size_t)(n0 + r) * HID + k0 + ch * 8]);
        }
    };
    issue(0, 0);  CP_COMMIT();
    issue(1, 64); CP_COMMIT();

    const int NK = HID / 64;  // 16
    for (int ko = 0; ko < NK; ko++) {
        CP_WAIT(1);
        __syncthreads();
        if (ko + 2 < NK) issue((ko + 2) % 3, (ko + 2) * 64);
        CP_COMMIT();
        uint32_t sa = sbase + (uint32_t)(ko % 3) * STAGE_B;
        compute32x64<4>(c, sa, sa + HTILE_B, 72, 0, wm, wn, lane);
    }
    CP_WAIT(0);
    __syncthreads();

    // stage tg*(c+bd) fp32 (stride 132 floats = 528B, 16B-aligned), coalesced epilogue
    const float tg = tanhf(gate[0]);
    float* sEpF = (float*)dyn;
    const int g = lane >> 2, t4 = lane & 3;
    #pragma unroll
    for (int mi = 0; mi < 2; mi++) {
        int r0 = wm * 32 + mi * 16 + g;
        #pragma unroll
        for (int nj = 0; nj < 8; nj++) {
            int cc = wn * 64 + nj * 8 + t4 * 2;
            float2 b2 = *(const float2*)&bd[n0 + cc];
            sEpF[r0 * 132 + cc]           = tg * (c[mi][nj][0] + b2.x);
            sEpF[r0 * 132 + cc + 1]       = tg * (c[mi][nj][1] + b2.y);
            sEpF[(r0 + 8) * 132 + cc]     = tg * (c[mi][nj][2] + b2.x);
            sEpF[(r0 + 8) * 132 + cc + 1] = tg * (c[mi][nj][3] + b2.y);
        }
    }
    __syncthreads();
    #pragma unroll
    for (int u = 0; u < 16; u++) {
        int idx = u * 256 + tid, r = idx >> 5, cc = (idx & 31) * 4;
        size_t go = (size_t)(m0 + r) * DIMD + n0 + cc;
        float4 d = *(float4*)&sEpF[r * 132 + cc];
        uint2 h2 = ldcs2u(&g_x0b[go]);
        uint2 l2 = ldcs2u(&g_x0lo[go]);
        float2 ha = __bfloat1622float2(*(__nv_bfloat162*)&h2.x);
        float2 hb = __bfloat1622float2(*(__nv_bfloat162*)&h2.y);
        float2 la = __bfloat1622float2(*(__nv_bfloat162*)&l2.x);
        float2 lb = __bfloat1622float2(*(__nv_bfloat162*)&l2.y);
        float y0 = ha.x + la.x + d.x;
        float y1 = ha.y + la.y + d.y;
        float y2 = hb.x + lb.x + d.z;
        float y3 = hb.y + lb.y + d.w;
        __nv_bfloat16 oh[4], ol[4];
        hilo(y0, oh[0], ol[0]); hilo(y1, oh[1], ol[1]);
        hilo(y2, oh[2], ol[2]); hilo(y3, oh[3], ol[3]);
        stcs2u(&g_x1b[go],  *(uint2*)oh);
        stcs2u(&g_x1lo[go], *(uint2*)ol);
    }
}

// ================= G3: VQ argmin (streamed A+B, 4 chunks) + fused epilogue =================
__global__ void __launch_bounds__(256, 2) g3_kernel(const float* __restrict__ mb,
                                                    float* __restrict__ out)
{
    extern __shared__ char dyn3[];
    const uint32_t sbase = smem_u32(dyn3);
    const int tid = threadIdx.x, lane = tid & 31, wid = tid >> 5;
    const int wm = wid & 3, wn = wid >> 2;
    const int m0 = blockIdx.x << 7;

    float bestv[4] = {3.4e38f, 3.4e38f, 3.4e38f, 3.4e38f};
    int   besti[4] = {0, 0, 0, 0};
    const int g = lane >> 2, t4 = lane & 3;
    const int rr = tid >> 3, ch = tid & 7;

    for (int nc = 0; nc < 4; nc++) {
        const int n0 = nc << 7;
        float c[2][8][4];
        #pragma unroll
        for (int i = 0; i < 2; i++)
            #pragma unroll
            for (int j = 0; j < 8; j++)
                #pragma unroll
                for (int q = 0; q < 4; q++) c[i][j][q] = 0.f;

        auto issue = [&](int stage, int k0) {
            uint32_t sa = sbase + stage * STAGE_B;
            uint32_t sb = sa + HTILE_B;
            #pragma unroll
            for (int u = 0; u < 4; u++) {
                int r = rr + u * 32;
                cp16(sa + (uint32_t)(r * 144 + ch * 16),
                     &g_x1b[(size_t)(m0 + r) * DIMD + k0 + ch * 8]);
                cp16(sb + (uint32_t)(r * 144 + ch * 16),
                     &g_mbb[(size_t)(n0 + r) * DIMD + k0 + ch * 8]);
            }
        };
        issue(0, 0);  CP_COMMIT();
        issue(1, 64); CP_COMMIT();

        const int NK = DIMD / 64;  // 8
        for (int ko = 0; ko < NK; ko++) {
            CP_WAIT(1);
            __syncthreads();
            if (ko + 2 < NK) issue((ko + 2) % 3, (ko + 2) * 64);
            CP_COMMIT();
            uint32_t sa = sbase + (uint32_t)(ko % 3) * STAGE_B;
            compute32x64<4>(c, sa, sa + HTILE_B, 72, 0, wm, wn, lane);
        }

        // score update: s = -2*(x.c) + ||c||^2 (cnorm via LDG, L2-hot)
        #pragma unroll
        for (int mi = 0; mi < 2; mi++)
            #pragma unroll
            for (int rj = 0; rj < 2; rj++) {
                int slot = mi * 2 + rj;
                #pragma unroll
                for (int nj = 0; nj < 8; nj++)
                    #pragma unroll
                    for (int jc = 0; jc < 2; jc++) {
                        int col = n0 + wn * 64 + nj * 8 + t4 * 2 + jc;
                        float sc = fmaf(-2.f, c[mi][nj][rj * 2 + jc], __ldg(&g_cnorm[col]));
                        if (sc < bestv[slot]) { bestv[slot] = sc; besti[slot] = col; }
                    }
            }
        __syncthreads();   // all warps done with stages before next chunk reuses them
    }
    CP_WAIT(0);

    // reduce best across lanes sharing a row; overlay pipeline smem
    float* sVal = (float*)dyn3;
    int*   sI2  = (int*)(dyn3 + 1024);
    int*   sIdx = (int*)(dyn3 + 2048);

    #pragma unroll
    for (int slot = 0; slot < 4; slot++) {
        float v = bestv[slot]; int ix = besti[slot];
        #pragma unroll
        for (int o = 1; o <= 2; o <<= 1) {
            float ov = __shfl_xor_sync(0xffffffffu, v, o);
            int   oi = __shfl_xor_sync(0xffffffffu, ix, o);
            if (ov < v || (ov == v && oi < ix)) { v = ov; ix = oi; }
        }
        bestv[slot] = v; besti[slot] = ix;
    }
    if (t4 == 0) {
        #pragma unroll
        for (int mi = 0; mi < 2; mi++)
            #pragma unroll
            for (int rj = 0; rj < 2; rj++) {
                int rl = wm * 32 + mi * 16 + g + rj * 8;
                sVal[wn * 128 + rl] = bestv[mi * 2 + rj];
                sI2[wn * 128 + rl]  = besti[mi * 2 + rj];
            }
    }
    __syncthreads();
    if (tid < 128) {
        float v0 = sVal[tid], v1 = sVal[128 + tid];
        int i0 = sI2[tid], i1 = sI2[128 + tid];
        sIdx[tid] = (v1 < v0 || (v1 == v0 && i1 < i0)) ? i1 : i0;
    }
    __syncthreads();

    // fused epilogue: x = (hi+lo) + 0.05*code; nan_to_num; norm clamp to 10
    for (int it = 0; it < 16; it++) {
        int rl = it * 8 + wid;
        int idx = sIdx[rl];
        size_t rbase = (size_t)(m0 + rl) * DIMD;
        size_t cbase = (size_t)idx * DIMD;
        float ss = 0.f;
        float4 vv[4];
        #pragma unroll
        for (int j = 0; j < 4; j++) {
            int col = j * 128 + lane * 4;
            uint2 h2 = ldcs2u(&g_x1b[rbase + col]);
            uint2 l2 = ldcs2u(&g_x1lo[rbase + col]);
            float4 cd = *(const float4*)&mb[cbase + col];
            float2 ha = __bfloat1622float2(*(__nv_bfloat162*)&h2.x);
            float2 hb = __bfloat1622float2(*(__nv_bfloat162*)&h2.y);
            float2 la = __bfloat1622float2(*(__nv_bfloat162*)&l2.x);
            float2 lb = __bfloat1622float2(*(__nv_bfloat162*)&l2.y);
            float a0 = fixv(ha.x + la.x + 0.05f * cd.x);
            float a1 = fixv(ha.y + la.y + 0.05f * cd.y);
            float a2 = fixv(hb.x + lb.x + 0.05f * cd.z);
            float a3 = fixv(hb.y + lb.y + 0.05f * cd.w);
            vv[j] = make_float4(a0, a1, a2, a3);
            ss += a0 * a0 + a1 * a1 + a2 * a2 + a3 * a3;
        }
        #pragma unroll
        for (int o = 16; o > 0; o >>= 1) ss += __shfl_xor_sync(0xffffffffu, ss, o);
        float nrm = sqrtf(ss);
        float scale = (nrm > 10.f) ? (10.f / fmaxf(nrm, 1e-6f)) : 1.f;
        #pragma unroll
        for (int j = 0; j < 4; j++) {
            int col = j * 128 + lane * 4;
            stcs4f(&out[rbase + col],
                   make_float4(vv[j].x * scale, vv[j].y * scale, vv[j].z * scale, vv[j].w * scale));
        }
    }
}

// ---------------- launch ----------------
extern "C" void kernel_launch(void* const* d_in, const int* in_sizes, int n_in,
                              void* d_out, int out_size) {
    const float* ie   = (const float*)d_in[0];
    const float* nb   = (const float*)d_in[1];
    const float* mu   = (const float*)d_in[2];
    const float* wu   = (const float*)d_in[3];
    const float* bu   = (const float*)d_in[4];
    const float* wd   = (const float*)d_in[5];
    const float* bd   = (const float*)d_in[6];
    const float* gate = (const float*)d_in[7];
    const float* mb   = (const float*)d_in[8];
    float* out = (float*)d_out;

    cudaFuncSetAttribute(g1_kernel, cudaFuncAttributeMaxDynamicSharedMemorySize, G12_DS);
    cudaFuncSetAttribute(g2_kernel, cudaFuncAttributeMaxDynamicSharedMemorySize, G12_DS);
    cudaFuncSetAttribute(g3_kernel, cudaFuncAttributeMaxDynamicSharedMemorySize, G3_DS);

    kpre<<<37952, 256>>>(ie, nb, mu, wu, wd, mb);
    g1_kernel<<<dim3(HID / 128, NROWS / 128), 256, G12_DS>>>(bu);
    g2_kernel<<<dim3(DIMD / 128, NROWS / 128), 256, G12_DS>>>(bd, gate);
    g3_kernel<<<NROWS / 128, 256, G3_DS>>>(mb, out);
}

// round 14
// speedup vs baseline: 1.0704x; 1.0704x over previous
#include <cuda_runtime.h>
#include <cuda_bf16.h>
#include <stdint.h>
#include <math.h>

#define NROWS 131072
#define DIMD  512
#define HID   1024
#define NMEM  512

// ---------------- scratch ----------------
__device__ __nv_bfloat16 g_h   [(size_t)NROWS * HID];
__device__ __nv_bfloat16 g_x0b [(size_t)NROWS * DIMD];  // hi(x0)
__device__ __nv_bfloat16 g_x0lo[(size_t)NROWS * DIMD];  // lo(x0)
__device__ __nv_bfloat16 g_x1b [(size_t)NROWS * DIMD];  // hi(x1)
__device__ __nv_bfloat16 g_x1lo[(size_t)NROWS * DIMD];  // lo(x1)
__device__ __nv_bfloat16 g_wub[(size_t)HID * DIMD];     // [n][k]
__device__ __nv_bfloat16 g_wdb[(size_t)DIMD * HID];     // [n][k]
__device__ __nv_bfloat16 g_mbb[(size_t)NMEM * DIMD];    // [code][k]
__device__ float         g_cnorm[NMEM];

// ---------------- helpers ----------------
static __device__ __forceinline__ uint32_t smem_u32(const void* p) {
    uint32_t a;
    asm("{ .reg .u64 t; cvta.to.shared.u64 t, %1; cvt.u32.u64 %0, t; }" : "=r"(a) : "l"(p));
    return a;
}
static __device__ __forceinline__ uint32_t f2bf2(float lo, float hi) {
    uint32_t r;
    asm("cvt.rn.bf16x2.f32 %0, %1, %2;" : "=r"(r) : "f"(hi), "f"(lo));
    return r;
}
static __device__ __forceinline__ void cp16(uint32_t saddr, const void* g) {
    asm volatile("cp.async.cg.shared.global [%0], [%1], 16;" :: "r"(saddr), "l"(g));
}
#define CP_COMMIT() asm volatile("cp.async.commit_group;" ::: "memory")
#define CP_WAIT(n)  asm volatile("cp.async.wait_group %0;" :: "n"(n) : "memory")

static __device__ __forceinline__ void ldsm4(uint32_t* a, uint32_t addr) {
    asm volatile("ldmatrix.sync.aligned.m8n8.x4.shared.b16 {%0,%1,%2,%3}, [%4];"
        : "=r"(a[0]), "=r"(a[1]), "=r"(a[2]), "=r"(a[3]) : "r"(addr));
}
static __device__ __forceinline__ void mma16816(float* c, const uint32_t* a, const uint32_t* b) {
    asm volatile("mma.sync.aligned.m16n8k16.row.col.f32.bf16.bf16.f32 "
        "{%0,%1,%2,%3}, {%4,%5,%6,%7}, {%8,%9}, {%0,%1,%2,%3};"
        : "+f"(c[0]), "+f"(c[1]), "+f"(c[2]), "+f"(c[3])
        : "r"(a[0]), "r"(a[1]), "r"(a[2]), "r"(a[3]), "r"(b[0]), "r"(b[1]));
}
static __device__ __forceinline__ float fixv(float x) {
    if (isnan(x)) return 0.f;
    if (isinf(x)) return x > 0.f ? 1.f : -1.f;
    return x;
}
static __device__ __forceinline__ void hilo(float v, __nv_bfloat16& h, __nv_bfloat16& l) {
    h = __float2bfloat16(v);
    l = __float2bfloat16(v - __bfloat162float(h));
}

// 32x64 warp tile, NKS*16 k per call. A stride astride elems (k-contig rows);
// B tile rows (n-major) stride 72 elems. c[2][8][4]. Warp (wm 0..3, wn 0..1).
template<int NKS>
static __device__ __forceinline__ void compute32x64(
    float c[2][8][4], uint32_t sAu, uint32_t sBu, int astride,
    int kbase, int wm, int wn, int lane)
{
    const int al = lane & 15, ah = (lane >> 4) << 3;
    const int bn = (lane & 7) + ((lane >> 4) << 3);
    const int bk = ((lane >> 3) & 1) << 3;
    #pragma unroll
    for (int ks = 0; ks < NKS; ks++) {
        const int koff = kbase + ks * 16;
        uint32_t a[2][4], bf[4][4];
        #pragma unroll
        for (int mi = 0; mi < 2; mi++) {
            uint32_t arow = (uint32_t)(wm * 32 + mi * 16 + al);
            ldsm4(a[mi], sAu + (arow * astride + koff + ah) * 2u);
        }
        #pragma unroll
        for (int p = 0; p < 4; p++) {
            uint32_t brow = (uint32_t)(wn * 64 + p * 16 + bn);
            ldsm4(bf[p], sBu + (brow * 72u + ks * 16 + bk) * 2u);
        }
        #pragma unroll
        for (int mi = 0; mi < 2; mi++)
            #pragma unroll
            for (int p = 0; p < 4; p++) {
                mma16816(c[mi][p * 2],     a[mi], &bf[p][0]);
                mma16816(c[mi][p * 2 + 1], a[mi], &bf[p][2]);
            }
    }
}

// ---------------- prep + combine (single launch) ----------------
// blocks [0,16384): combine x0 (16 elems/thread); [16384,18432): wub;
// [18432,20480): wdb; [20480,21504): mbb; [21504,21568): cnorm
__global__ void __launch_bounds__(256) kpre(const float* __restrict__ ie,
                                            const float* __restrict__ nb,
                                            const float* __restrict__ mu,
                                            const float* __restrict__ wu,
                                            const float* __restrict__ wd,
                                            const float* __restrict__ mb)
{
    int b = blockIdx.x;
    if (b < 16384) {
        size_t base = ((size_t)b * 256 + threadIdx.x) * 16;
        int kcol = (int)(base & (DIMD - 1));
        #pragma unroll
        for (int half = 0; half < 2; half++) {
            size_t off = base + half * 8;
            int kc = kcol + half * 8;
            float4 e0 = *(const float4*)(ie + off);
            float4 e1 = *(const float4*)(ie + off + 4);
            float4 n0 = *(const float4*)(nb + off);
            float4 n1 = *(const float4*)(nb + off + 4);
            float4 m0 = *(const float4*)(mu + kc);
            float4 m1 = *(const float4*)(mu + kc + 4);
            float v[8];
            v[0] = e0.x + 0.1f * n0.x + m0.x;
            v[1] = e0.y + 0.1f * n0.y + m0.y;
            v[2] = e0.z + 0.1f * n0.z + m0.z;
            v[3] = e0.w + 0.1f * n0.w + m0.w;
            v[4] = e1.x + 0.1f * n1.x + m1.x;
            v[5] = e1.y + 0.1f * n1.y + m1.y;
            v[6] = e1.z + 0.1f * n1.z + m1.z;
            v[7] = e1.w + 0.1f * n1.w + m1.w;
            __nv_bfloat16 h[8], l[8];
            #pragma unroll
            for (int i = 0; i < 8; i++) hilo(v[i], h[i], l[i]);
            *(uint4*)(g_x0b  + off) = *(uint4*)h;
            *(uint4*)(g_x0lo + off) = *(uint4*)l;
        }
    } else if (b < 18432) {
        int i = (b - 16384) * 256 + threadIdx.x;
        int n = i >> 9, k = i & 511;
        g_wub[i] = __float2bfloat16(wu[(size_t)k * HID + n]);
    } else if (b < 20480) {
        int i = (b - 18432) * 256 + threadIdx.x;
        int n = i >> 10, k = i & 1023;
        g_wdb[i] = __float2bfloat16(wd[(size_t)k * DIMD + n]);
    } else if (b < 21504) {
        int i = (b - 20480) * 256 + threadIdx.x;
        g_mbb[i] = __float2bfloat16(mb[i]);
    } else {
        int code = (b - 21504) * 8 + (threadIdx.x >> 5);
        int lane = threadIdx.x & 31;
        float s = 0.f;
        #pragma unroll
        for (int t = 0; t < 16; t++) {
            float v = mb[(size_t)code * DIMD + t * 32 + lane];
            s += v * v;
        }
        #pragma unroll
        for (int o = 16; o > 0; o >>= 1) s += __shfl_xor_sync(0xffffffffu, s, o);
        if (lane == 0) g_cnorm[code] = s;
    }
}

// BK=64 tiles: 128x72 bf16 = 18432 B per operand; 3 stages of (A|B).
#define HTILE_B 18432
#define STAGE_B (2 * HTILE_B)
#define G12_DS  (3 * STAGE_B)      // 110592
#define G3_DS   (G12_DS + 2048)    // + cnorm region

// ================= G1: h = silu(x0b @ Wu^T + bu) =================
__global__ void __launch_bounds__(256, 2) g1_kernel(const float* __restrict__ bu)
{
    extern __shared__ char dyn[];
    const uint32_t sbase = smem_u32(dyn);
    const int tid = threadIdx.x, lane = tid & 31, wid = tid >> 5;
    const int wm = wid & 3, wn = wid >> 2;
    const int m0 = blockIdx.y << 7, n0 = blockIdx.x << 7;

    float c[2][8][4];
    #pragma unroll
    for (int i = 0; i < 2; i++)
        #pragma unroll
        for (int j = 0; j < 8; j++)
            #pragma unroll
            for (int q = 0; q < 4; q++) c[i][j][q] = 0.f;

    const int rr = tid >> 3, ch = tid & 7;
    auto issue = [&](int stage, int k0) {
        uint32_t sa = sbase + stage * STAGE_B;
        uint32_t sb = sa + HTILE_B;
        #pragma unroll
        for (int u = 0; u < 4; u++) {
            int r = rr + u * 32;
            cp16(sa + (uint32_t)(r * 144 + ch * 16), &g_x0b[(size_t)(m0 + r) * DIMD + k0 + ch * 8]);
            cp16(sb + (uint32_t)(r * 144 + ch * 16), &g_wub[(size_t)(n0 + r) * DIMD + k0 + ch * 8]);
        }
    };
    issue(0, 0);  CP_COMMIT();
    issue(1, 64); CP_COMMIT();

    const int NK = DIMD / 64;  // 8
    for (int ko = 0; ko < NK; ko++) {
        CP_WAIT(1);
        __syncthreads();
        if (ko + 2 < NK) issue((ko + 2) % 3, (ko + 2) * 64);
        CP_COMMIT();
        uint32_t sa = sbase + (uint32_t)(ko % 3) * STAGE_B;
        compute32x64<4>(c, sa, sa + HTILE_B, 72, 0, wm, wn, lane);
    }
    CP_WAIT(0);
    __syncthreads();

    // stage h tile bf16 (stride 136 -> 272B rows, 16B-aligned), coalesced copy out
    __nv_bfloat16* sEp = (__nv_bfloat16*)dyn;
    const int g = lane >> 2, t4 = lane & 3;
    #pragma unroll
    for (int mi = 0; mi < 2; mi++) {
        int r0 = wm * 32 + mi * 16 + g;
        #pragma unroll
        for (int nj = 0; nj < 8; nj++) {
            int cc = wn * 64 + nj * 8 + t4 * 2;
            float2 b2 = *(const float2*)&bu[n0 + cc];
            float v0 = c[mi][nj][0] + b2.x;
            float v1 = c[mi][nj][1] + b2.y;
            float v2 = c[mi][nj][2] + b2.x;
            float v3 = c[mi][nj][3] + b2.y;
            v0 = v0 / (1.f + __expf(-v0));
            v1 = v1 / (1.f + __expf(-v1));
            v2 = v2 / (1.f + __expf(-v2));
            v3 = v3 / (1.f + __expf(-v3));
            *(uint32_t*)&sEp[r0 * 136 + cc]       = f2bf2(v0, v1);
            *(uint32_t*)&sEp[(r0 + 8) * 136 + cc] = f2bf2(v2, v3);
        }
    }
    __syncthreads();
    #pragma unroll
    for (int u = 0; u < 8; u++) {
        int idx = u * 256 + tid, r = idx >> 4, cc = (idx & 15) * 8;
        *(uint4*)&g_h[(size_t)(m0 + r) * HID + n0 + cc] = *(uint4*)&sEp[r * 136 + cc];
    }
}

// ================= G2: x1 = x0 + tanh(gate) * (h @ Wd^T + bd), hi/lo out =================
__global__ void __launch_bounds__(256, 2) g2_kernel(const float* __restrict__ bd,
                                                    const float* __restrict__ gate)
{
    extern __shared__ char dyn[];
    const uint32_t sbase = smem_u32(dyn);
    const int tid = threadIdx.x, lane = tid & 31, wid = tid >> 5;
    const int wm = wid & 3, wn = wid >> 2;
    const int m0 = blockIdx.y << 7, n0 = blockIdx.x << 7;

    float c[2][8][4];
    #pragma unroll
    for (int i = 0; i < 2; i++)
        #pragma unroll
        for (int j = 0; j < 8; j++)
            #pragma unroll
            for (int q = 0; q < 4; q++) c[i][j][q] = 0.f;

    const int rr = tid >> 3, ch = tid & 7;
    auto issue = [&](int stage, int k0) {
        uint32_t sa = sbase + stage * STAGE_B;
        uint32_t sb = sa + HTILE_B;
        #pragma unroll
        for (int u = 0; u < 4; u++) {
            int r = rr + u * 32;
            cp16(sa + (uint32_t)(r * 144 + ch * 16), &g_h[(size_t)(m0 + r) * HID + k0 + ch * 8]);
            cp16(sb + (uint32_t)(r * 144 + ch * 16), &g_wdb[(size_t)(n0 + r) * HID + k0 + ch * 8]);
        }
    };
    issue(0, 0);  CP_COMMIT();
    issue(1, 64); CP_COMMIT();

    const int NK = HID / 64;  // 16
    for (int ko = 0; ko < NK; ko++) {
        CP_WAIT(1);
        __syncthreads();
        if (ko + 2 < NK) issue((ko + 2) % 3, (ko + 2) * 64);
        CP_COMMIT();
        uint32_t sa = sbase + (uint32_t)(ko % 3) * STAGE_B;
        compute32x64<4>(c, sa, sa + HTILE_B, 72, 0, wm, wn, lane);
    }
    CP_WAIT(0);
    __syncthreads();

    // stage tg*(c+bd) fp32 (stride 132 floats = 528B, 16B-aligned), coalesced epilogue
    const float tg = tanhf(gate[0]);
    float* sEpF = (float*)dyn;
    const int g = lane >> 2, t4 = lane & 3;
    #pragma unroll
    for (int mi = 0; mi < 2; mi++) {
        int r0 = wm * 32 + mi * 16 + g;
        #pragma unroll
        for (int nj = 0; nj < 8; nj++) {
            int cc = wn * 64 + nj * 8 + t4 * 2;
            float2 b2 = *(const float2*)&bd[n0 + cc];
            sEpF[r0 * 132 + cc]           = tg * (c[mi][nj][0] + b2.x);
            sEpF[r0 * 132 + cc + 1]       = tg * (c[mi][nj][1] + b2.y);
            sEpF[(r0 + 8) * 132 + cc]     = tg * (c[mi][nj][2] + b2.x);
            sEpF[(r0 + 8) * 132 + cc + 1] = tg * (c[mi][nj][3] + b2.y);
        }
    }
    __syncthreads();
    #pragma unroll
    for (int u = 0; u < 16; u++) {
        int idx = u * 256 + tid, r = idx >> 5, cc = (idx & 31) * 4;
        size_t go = (size_t)(m0 + r) * DIMD + n0 + cc;
        float4 d = *(float4*)&sEpF[r * 132 + cc];
        uint2 h2 = *(const uint2*)&g_x0b[go];
        uint2 l2 = *(const uint2*)&g_x0lo[go];
        float2 ha = __bfloat1622float2(*(__nv_bfloat162*)&h2.x);
        float2 hb = __bfloat1622float2(*(__nv_bfloat162*)&h2.y);
        float2 la = __bfloat1622float2(*(__nv_bfloat162*)&l2.x);
        float2 lb = __bfloat1622float2(*(__nv_bfloat162*)&l2.y);
        float y0 = ha.x + la.x + d.x;
        float y1 = ha.y + la.y + d.y;
        float y2 = hb.x + lb.x + d.z;
        float y3 = hb.y + lb.y + d.w;
        __nv_bfloat16 oh[4], ol[4];
        hilo(y0, oh[0], ol[0]); hilo(y1, oh[1], ol[1]);
        hilo(y2, oh[2], ol[2]); hilo(y3, oh[3], ol[3]);
        *(uint2*)&g_x1b[go]  = *(uint2*)oh;
        *(uint2*)&g_x1lo[go] = *(uint2*)ol;
    }
}

// ================= G3: VQ argmin (flat 32-iter pipeline) + fused epilogue =================
__global__ void __launch_bounds__(256, 2) g3_kernel(const float* __restrict__ mb,
                                                    float* __restrict__ out)
{
    extern __shared__ char dyn3[];
    const uint32_t sbase = smem_u32(dyn3);
    float* scn = (float*)(dyn3 + G12_DS);
    const int tid = threadIdx.x, lane = tid & 31, wid = tid >> 5;
    const int wm = wid & 3, wn = wid >> 2;
    const int m0 = blockIdx.x << 7;

    for (int i = tid; i < NMEM; i += 256) scn[i] = g_cnorm[i];

    float bestv[4] = {3.4e38f, 3.4e38f, 3.4e38f, 3.4e38f};
    int   besti[4] = {0, 0, 0, 0};
    float c[2][8][4];
    #pragma unroll
    for (int i = 0; i < 2; i++)
        #pragma unroll
        for (int j = 0; j < 8; j++)
            #pragma unroll
            for (int q = 0; q < 4; q++) c[i][j][q] = 0.f;

    const int g = lane >> 2, t4 = lane & 3;
    const int rr = tid >> 3, ch = tid & 7;

    auto issue = [&](int it) {
        int stage = it % 3;
        int k0 = (it & 7) << 6;
        int nb0 = (it >> 3) << 7;
        uint32_t sa = sbase + stage * STAGE_B;
        uint32_t sb = sa + HTILE_B;
        #pragma unroll
        for (int u = 0; u < 4; u++) {
            int r = rr + u * 32;
            cp16(sa + (uint32_t)(r * 144 + ch * 16),
                 &g_x1b[(size_t)(m0 + r) * DIMD + k0 + ch * 8]);
            cp16(sb + (uint32_t)(r * 144 + ch * 16),
                 &g_mbb[(size_t)(nb0 + r) * DIMD + k0 + ch * 8]);
        }
    };
    issue(0); CP_COMMIT();
    issue(1); CP_COMMIT();

    for (int it = 0; it < 32; it++) {
        CP_WAIT(1);
        __syncthreads();
        if (it + 2 < 32) issue(it + 2);
        CP_COMMIT();
        uint32_t sa = sbase + (uint32_t)(it % 3) * STAGE_B;
        compute32x64<4>(c, sa, sa + HTILE_B, 72, 0, wm, wn, lane);
        if ((it & 7) == 7) {
            int nb0 = (it >> 3) << 7;
            #pragma unroll
            for (int mi = 0; mi < 2; mi++)
                #pragma unroll
                for (int rj = 0; rj < 2; rj++) {
                    int slot = mi * 2 + rj;
                    #pragma unroll
                    for (int nj = 0; nj < 8; nj++)
                        #pragma unroll
                        for (int jc = 0; jc < 2; jc++) {
                            int col = nb0 + wn * 64 + nj * 8 + t4 * 2 + jc;
                            float sc = fmaf(-2.f, c[mi][nj][rj * 2 + jc], scn[col]);
                            if (sc < bestv[slot]) { bestv[slot] = sc; besti[slot] = col; }
                        }
                }
            #pragma unroll
            for (int i = 0; i < 2; i++)
                #pragma unroll
                for (int j = 0; j < 8; j++)
                    #pragma unroll
                    for (int q = 0; q < 4; q++) c[i][j][q] = 0.f;
        }
    }
    CP_WAIT(0);
    __syncthreads();

    float* sVal = (float*)dyn3;
    int*   sI2  = (int*)(dyn3 + 1024);
    int*   sIdx = (int*)(dyn3 + 2048);

    #pragma unroll
    for (int slot = 0; slot < 4; slot++) {
        float v = bestv[slot]; int ix = besti[slot];
        #pragma unroll
        for (int o = 1; o <= 2; o <<= 1) {
            float ov = __shfl_xor_sync(0xffffffffu, v, o);
            int   oi = __shfl_xor_sync(0xffffffffu, ix, o);
            if (ov < v || (ov == v && oi < ix)) { v = ov; ix = oi; }
        }
        bestv[slot] = v; besti[slot] = ix;
    }
    if (t4 == 0) {
        #pragma unroll
        for (int mi = 0; mi < 2; mi++)
            #pragma unroll
            for (int rj = 0; rj < 2; rj++) {
                int rl = wm * 32 + mi * 16 + g + rj * 8;
                sVal[wn * 128 + rl] = bestv[mi * 2 + rj];
                sI2[wn * 128 + rl]  = besti[mi * 2 + rj];
            }
    }
    __syncthreads();
    if (tid < 128) {
        float v0 = sVal[tid], v1 = sVal[128 + tid];
        int i0 = sI2[tid], i1 = sI2[128 + tid];
        sIdx[tid] = (v1 < v0 || (v1 == v0 && i1 < i0)) ? i1 : i0;
    }
    __syncthreads();

    for (int it = 0; it < 16; it++) {
        int rl = it * 8 + wid;
        int idx = sIdx[rl];
        size_t rbase = (size_t)(m0 + rl) * DIMD;
        size_t cbase = (size_t)idx * DIMD;
        float ss = 0.f;
        float4 vv[4];
        #pragma unroll
        for (int j = 0; j < 4; j++) {
            int col = j * 128 + lane * 4;
            uint2 h2 = *(const uint2*)&g_x1b[rbase + col];
            uint2 l2 = *(const uint2*)&g_x1lo[rbase + col];
            float4 cd = *(const float4*)&mb[cbase + col];
            float2 ha = __bfloat1622float2(*(__nv_bfloat162*)&h2.x);
            float2 hb = __bfloat1622float2(*(__nv_bfloat162*)&h2.y);
            float2 la = __bfloat1622float2(*(__nv_bfloat162*)&l2.x);
            float2 lb = __bfloat1622float2(*(__nv_bfloat162*)&l2.y);
            float a0 = fixv(ha.x + la.x + 0.05f * cd.x);
            float a1 = fixv(ha.y + la.y + 0.05f * cd.y);
            float a2 = fixv(hb.x + lb.x + 0.05f * cd.z);
            float a3 = fixv(hb.y + lb.y + 0.05f * cd.w);
            vv[j] = make_float4(a0, a1, a2, a3);
            ss += a0 * a0 + a1 * a1 + a2 * a2 + a3 * a3;
        }
        #pragma unroll
        for (int o = 16; o > 0; o >>= 1) ss += __shfl_xor_sync(0xffffffffu, ss, o);
        float nrm = sqrtf(ss);
        float scale = (nrm > 10.f) ? (10.f / fmaxf(nrm, 1e-6f)) : 1.f;
        #pragma unroll
        for (int j = 0; j < 4; j++) {
            int col = j * 128 + lane * 4;
            *(float4*)&out[rbase + col] =
                make_float4(vv[j].x * scale, vv[j].y * scale, vv[j].z * scale, vv[j].w * scale);
        }
    }
}

// ---------------- launch ----------------
extern "C" void kernel_launch(void* const* d_in, const int* in_sizes, int n_in,
                              void* d_out, int out_size) {
    const float* ie   = (const float*)d_in[0];
    const float* nb   = (const float*)d_in[1];
    const float* mu   = (const float*)d_in[2];
    const float* wu   = (const float*)d_in[3];
    const float* bu   = (const float*)d_in[4];
    const float* wd   = (const float*)d_in[5];
    const float* bd   = (const float*)d_in[6];
    const float* gate = (const float*)d_in[7];
    const float* mb   = (const float*)d_in[8];
    float* out = (float*)d_out;

    cudaFuncSetAttribute(g1_kernel, cudaFuncAttributeMaxDynamicSharedMemorySize, G12_DS);
    cudaFuncSetAttribute(g2_kernel, cudaFuncAttributeMaxDynamicSharedMemorySize, G12_DS);
    cudaFuncSetAttribute(g3_kernel, cudaFuncAttributeMaxDynamicSharedMemorySize, G3_DS);

    kpre<<<21568, 256>>>(ie, nb, mu, wu, wd, mb);
    g1_kernel<<<dim3(HID / 128, NROWS / 128), 256, G12_DS>>>(bu);
    g2_kernel<<<dim3(DIMD / 128, NROWS / 128), 256, G12_DS>>>(bd, gate);
    g3_kernel<<<NROWS / 128, 256, G3_DS>>>(mb, out);
}

// round 15
// speedup vs baseline: 1.1151x; 1.0417x over previous
#include <cuda_runtime.h>
#include <cuda_bf16.h>
#include <cuda_fp8.h>
#include <stdint.h>
#include <math.h>

#define NROWS 131072
#define DIMD  512
#define HID   1024
#define NMEM  512

// ---------------- scratch ----------------
__device__ uint8_t       g_h8  [(size_t)NROWS * HID];   // h in e4m3 (128 MB)
__device__ __nv_bfloat16 g_x0b [(size_t)NROWS * DIMD];  // hi(x0)
__device__ __nv_bfloat16 g_x0lo[(size_t)NROWS * DIMD];  // lo(x0)
__device__ __nv_bfloat16 g_x1b [(size_t)NROWS * DIMD];  // hi(x1)
__device__ __nv_bfloat16 g_x1lo[(size_t)NROWS * DIMD];  // lo(x1)
__device__ __nv_bfloat16 g_wub[(size_t)HID * DIMD];     // [n][k] bf16
__device__ uint8_t       g_wd8[(size_t)DIMD * HID];     // [n][k] e4m3
__device__ __nv_bfloat16 g_mbb[(size_t)NMEM * DIMD];    // [code][k] bf16
__device__ float         g_cnorm[NMEM];

// ---------------- helpers ----------------
static __device__ __forceinline__ uint32_t smem_u32(const void* p) {
    uint32_t a;
    asm("{ .reg .u64 t; cvta.to.shared.u64 t, %1; cvt.u32.u64 %0, t; }" : "=r"(a) : "l"(p));
    return a;
}
static __device__ __forceinline__ uint32_t f2bf2(float lo, float hi) {
    uint32_t r;
    asm("cvt.rn.bf16x2.f32 %0, %1, %2;" : "=r"(r) : "f"(hi), "f"(lo));
    return r;
}
static __device__ __forceinline__ unsigned short f2e4m3x2(float lo, float hi) {
    unsigned short r;
    asm("cvt.rn.satfinite.e4m3x2.f32 %0, %1, %2;" : "=h"(r) : "f"(hi), "f"(lo));
    return r;
}
static __device__ __forceinline__ void cp16(uint32_t saddr, const void* g) {
    asm volatile("cp.async.cg.shared.global [%0], [%1], 16;" :: "r"(saddr), "l"(g));
}
#define CP_COMMIT() asm volatile("cp.async.commit_group;" ::: "memory")
#define CP_WAIT(n)  asm volatile("cp.async.wait_group %0;" :: "n"(n) : "memory")

static __device__ __forceinline__ void ldsm4(uint32_t* a, uint32_t addr) {
    asm volatile("ldmatrix.sync.aligned.m8n8.x4.shared.b16 {%0,%1,%2,%3}, [%4];"
        : "=r"(a[0]), "=r"(a[1]), "=r"(a[2]), "=r"(a[3]) : "r"(addr));
}
static __device__ __forceinline__ void mma16816(float* c, const uint32_t* a, const uint32_t* b) {
    asm volatile("mma.sync.aligned.m16n8k16.row.col.f32.bf16.bf16.f32 "
        "{%0,%1,%2,%3}, {%4,%5,%6,%7}, {%8,%9}, {%0,%1,%2,%3};"
        : "+f"(c[0]), "+f"(c[1]), "+f"(c[2]), "+f"(c[3])
        : "r"(a[0]), "r"(a[1]), "r"(a[2]), "r"(a[3]), "r"(b[0]), "r"(b[1]));
}
static __device__ __forceinline__ void mma16832f8(float* c, const uint32_t* a, const uint32_t* b) {
    asm volatile("mma.sync.aligned.m16n8k32.row.col.f32.e4m3.e4m3.f32 "
        "{%0,%1,%2,%3}, {%4,%5,%6,%7}, {%8,%9}, {%0,%1,%2,%3};"
        : "+f"(c[0]), "+f"(c[1]), "+f"(c[2]), "+f"(c[3])
        : "r"(a[0]), "r"(a[1]), "r"(a[2]), "r"(a[3]), "r"(b[0]), "r"(b[1]));
}
static __device__ __forceinline__ float fixv(float x) {
    if (isnan(x)) return 0.f;
    if (isinf(x)) return x > 0.f ? 1.f : -1.f;
    return x;
}
static __device__ __forceinline__ void hilo(float v, __nv_bfloat16& h, __nv_bfloat16& l) {
    h = __float2bfloat16(v);
    l = __float2bfloat16(v - __bfloat162float(h));
}

// bf16 32x64 warp tile, NKS*16 k per call. A stride astride elems; B rows stride 72 elems.
template<int NKS>
static __device__ __forceinline__ void compute32x64(
    float c[2][8][4], uint32_t sAu, uint32_t sBu, int astride,
    int kbase, int wm, int wn, int lane)
{
    const int al = lane & 15, ah = (lane >> 4) << 3;
    const int bn = (lane & 7) + ((lane >> 4) << 3);
    const int bk = ((lane >> 3) & 1) << 3;
    #pragma unroll
    for (int ks = 0; ks < NKS; ks++) {
        const int koff = kbase + ks * 16;
        uint32_t a[2][4], bf[4][4];
        #pragma unroll
        for (int mi = 0; mi < 2; mi++) {
            uint32_t arow = (uint32_t)(wm * 32 + mi * 16 + al);
            ldsm4(a[mi], sAu + (arow * astride + koff + ah) * 2u);
        }
        #pragma unroll
        for (int p = 0; p < 4; p++) {
            uint32_t brow = (uint32_t)(wn * 64 + p * 16 + bn);
            ldsm4(bf[p], sBu + (brow * 72u + ks * 16 + bk) * 2u);
        }
        #pragma unroll
        for (int mi = 0; mi < 2; mi++)
            #pragma unroll
            for (int p = 0; p < 4; p++) {
                mma16816(c[mi][p * 2],     a[mi], &bf[p][0]);
                mma16816(c[mi][p * 2 + 1], a[mi], &bf[p][2]);
            }
    }
}

// fp8 32x64 warp tile, NKS*32 k per call. A and B tiles: 144-byte rows (128 fp8 + pad).
template<int NKS>
static __device__ __forceinline__ void compute32x64_f8(
    float c[2][8][4], uint32_t sAu, uint32_t sBu, int wm, int wn, int lane)
{
    const int al = lane & 15, ah = (lane >> 4) << 4;       // bytes
    const int bn = (lane & 7) + ((lane >> 4) << 3);
    const int bk = ((lane >> 3) & 1) << 4;                 // bytes
    #pragma unroll
    for (int ks = 0; ks < NKS; ks++) {
        const int koff = ks * 32;                          // bytes
        uint32_t a[2][4], bf[4][4];
        #pragma unroll
        for (int mi = 0; mi < 2; mi++) {
            uint32_t arow = (uint32_t)(wm * 32 + mi * 16 + al);
            ldsm4(a[mi], sAu + arow * 144u + koff + ah);
        }
        #pragma unroll
        for (int p = 0; p < 4; p++) {
            uint32_t brow = (uint32_t)(wn * 64 + p * 16 + bn);
            ldsm4(bf[p], sBu + brow * 144u + koff + bk);
        }
        #pragma unroll
        for (int mi = 0; mi < 2; mi++)
            #pragma unroll
            for (int p = 0; p < 4; p++) {
                mma16832f8(c[mi][p * 2],     a[mi], &bf[p][0]);
                mma16832f8(c[mi][p * 2 + 1], a[mi], &bf[p][2]);
            }
    }
}

// ---------------- prep + combine (single launch) ----------------
// blocks [0,32768): combine x0 hi/lo; [32768,34816): wub; [34816,36864): wd8;
// [36864,37888): mbb; [37888,37952): cnorm
__global__ void __launch_bounds__(256) kpre(const float* __restrict__ ie,
                                            const float* __restrict__ nb,
                                            const float* __restrict__ mu,
                                            const float* __restrict__ wu,
                                            const float* __restrict__ wd,
                                            const float* __restrict__ mb)
{
    int b = blockIdx.x;
    if (b < 32768) {
        size_t base = ((size_t)b * 256 + threadIdx.x) * 8;
        int kcol = (int)(base & (DIMD - 1));
        float4 e0 = *(const float4*)(ie + base);
        float4 e1 = *(const float4*)(ie + base + 4);
        float4 n0 = *(const float4*)(nb + base);
        float4 n1 = *(const float4*)(nb + base + 4);
        float4 m0 = *(const float4*)(mu + kcol);
        float4 m1 = *(const float4*)(mu + kcol + 4);
        float v[8];
        v[0] = e0.x + 0.1f * n0.x + m0.x;
        v[1] = e0.y + 0.1f * n0.y + m0.y;
        v[2] = e0.z + 0.1f * n0.z + m0.z;
        v[3] = e0.w + 0.1f * n0.w + m0.w;
        v[4] = e1.x + 0.1f * n1.x + m1.x;
        v[5] = e1.y + 0.1f * n1.y + m1.y;
        v[6] = e1.z + 0.1f * n1.z + m1.z;
        v[7] = e1.w + 0.1f * n1.w + m1.w;
        __nv_bfloat16 h[8], l[8];
        #pragma unroll
        for (int i = 0; i < 8; i++) hilo(v[i], h[i], l[i]);
        *(uint4*)(g_x0b  + base) = *(uint4*)h;
        *(uint4*)(g_x0lo + base) = *(uint4*)l;
    } else if (b < 34816) {
        int i = (b - 32768) * 256 + threadIdx.x;
        int n = i >> 9, k = i & 511;
        g_wub[i] = __float2bfloat16(wu[(size_t)k * HID + n]);
    } else if (b < 36864) {
        int i = (b - 34816) * 256 + threadIdx.x;
        // two elements per thread (wd8 has 512*1024 = 524288 elems; 2048 blocks * 256 = 524288)
        int n = i >> 10, k = i & 1023;
        unsigned short p = f2e4m3x2(wd[(size_t)k * DIMD + n], 0.f);
        g_wd8[i] = (uint8_t)(p & 0xFF);
    } else if (b < 37888) {
        int i = (b - 36864) * 256 + threadIdx.x;
        g_mbb[i] = __float2bfloat16(mb[i]);
    } else {
        int code = (b - 37888) * 8 + (threadIdx.x >> 5);
        int lane = threadIdx.x & 31;
        float s = 0.f;
        #pragma unroll
        for (int t = 0; t < 16; t++) {
            float v = mb[(size_t)code * DIMD + t * 32 + lane];
            s += v * v;
        }
        #pragma unroll
        for (int o = 16; o > 0; o >>= 1) s += __shfl_xor_sync(0xffffffffu, s, o);
        if (lane == 0) g_cnorm[code] = s;
    }
}

// bf16 tiles: 128 rows x 72 elems (144 B) = 18432 B; fp8 tiles: 128 rows x 144 B = 18432 B.
#define HTILE_B 18432
#define STAGE_B (2 * HTILE_B)
#define G12_DS  (3 * STAGE_B)      // 110592
#define G3_DS   (G12_DS + 2048)

// ================= G1: h = silu(x0b @ Wu^T + bu) -> e4m3 =================
__global__ void __launch_bounds__(256, 2) g1_kernel(const float* __restrict__ bu)
{
    extern __shared__ char dyn[];
    const uint32_t sbase = smem_u32(dyn);
    const int tid = threadIdx.x, lane = tid & 31, wid = tid >> 5;
    const int wm = wid & 3, wn = wid >> 2;
    const int m0 = blockIdx.y << 7, n0 = blockIdx.x << 7;

    float c[2][8][4];
    #pragma unroll
    for (int i = 0; i < 2; i++)
        #pragma unroll
        for (int j = 0; j < 8; j++)
            #pragma unroll
            for (int q = 0; q < 4; q++) c[i][j][q] = 0.f;

    const int rr = tid >> 3, ch = tid & 7;
    auto issue = [&](int stage, int k0) {
        uint32_t sa = sbase + stage * STAGE_B;
        uint32_t sb = sa + HTILE_B;
        #pragma unroll
        for (int u = 0; u < 4; u++) {
            int r = rr + u * 32;
            cp16(sa + (uint32_t)(r * 144 + ch * 16), &g_x0b[(size_t)(m0 + r) * DIMD + k0 + ch * 8]);
            cp16(sb + (uint32_t)(r * 144 + ch * 16), &g_wub[(size_t)(n0 + r) * DIMD + k0 + ch * 8]);
        }
    };
    issue(0, 0);  CP_COMMIT();
    issue(1, 64); CP_COMMIT();

    const int NK = DIMD / 64;  // 8
    for (int ko = 0; ko < NK; ko++) {
        CP_WAIT(1);
        __syncthreads();
        if (ko + 2 < NK) issue((ko + 2) % 3, (ko + 2) * 64);
        CP_COMMIT();
        uint32_t sa = sbase + (uint32_t)(ko % 3) * STAGE_B;
        compute32x64<4>(c, sa, sa + HTILE_B, 72, 0, wm, wn, lane);
    }
    CP_WAIT(0);
    __syncthreads();

    // stage h tile e4m3 (144-byte rows, 16B-aligned), coalesced copy out
    uint8_t* sEp = (uint8_t*)dyn;
    const int g = lane >> 2, t4 = lane & 3;
    #pragma unroll
    for (int mi = 0; mi < 2; mi++) {
        int r0 = wm * 32 + mi * 16 + g;
        #pragma unroll
        for (int nj = 0; nj < 8; nj++) {
            int cc = wn * 64 + nj * 8 + t4 * 2;
            float2 b2 = *(const float2*)&bu[n0 + cc];
            float v0 = c[mi][nj][0] + b2.x;
            float v1 = c[mi][nj][1] + b2.y;
            float v2 = c[mi][nj][2] + b2.x;
            float v3 = c[mi][nj][3] + b2.y;
            v0 = v0 / (1.f + __expf(-v0));
            v1 = v1 / (1.f + __expf(-v1));
            v2 = v2 / (1.f + __expf(-v2));
            v3 = v3 / (1.f + __expf(-v3));
            *(unsigned short*)&sEp[r0 * 144 + cc]       = f2e4m3x2(v0, v1);
            *(unsigned short*)&sEp[(r0 + 8) * 144 + cc] = f2e4m3x2(v2, v3);
        }
    }
    __syncthreads();
    #pragma unroll
    for (int u = 0; u < 4; u++) {
        int idx = u * 256 + tid, r = idx >> 3, cc = (idx & 7) * 16;
        *(uint4*)&g_h8[(size_t)(m0 + r) * HID + n0 + cc] = *(uint4*)&sEp[r * 144 + cc];
    }
}

// ================= G2: x1 = x0 + tanh(gate) * (h @ Wd^T + bd)  [fp8 MMA] =================
__global__ void __launch_bounds__(256, 2) g2_kernel(const float* __restrict__ bd,
                                                    const float* __restrict__ gate)
{
    extern __shared__ char dyn[];
    const uint32_t sbase = smem_u32(dyn);
    const int tid = threadIdx.x, lane = tid & 31, wid = tid >> 5;
    const int wm = wid & 3, wn = wid >> 2;
    const int m0 = blockIdx.y << 7, n0 = blockIdx.x << 7;

    float c[2][8][4];
    #pragma unroll
    for (int i = 0; i < 2; i++)
        #pragma unroll
        for (int j = 0; j < 8; j++)
            #pragma unroll
            for (int q = 0; q < 4; q++) c[i][j][q] = 0.f;

    const int rr = tid >> 3, ch = tid & 7;
    auto issue = [&](int stage, int k0) {   // k0 in fp8 elems, step 128
        uint32_t sa = sbase + stage * STAGE_B;
        uint32_t sb = sa + HTILE_B;
        #pragma unroll
        for (int u = 0; u < 4; u++) {
            int r = rr + u * 32;
            cp16(sa + (uint32_t)(r * 144 + ch * 16), &g_h8[(size_t)(m0 + r) * HID + k0 + ch * 16]);
            cp16(sb + (uint32_t)(r * 144 + ch * 16), &g_wd8[(size_t)(n0 + r) * HID + k0 + ch * 16]);
        }
    };
    issue(0, 0);   CP_COMMIT();
    issue(1, 128); CP_COMMIT();

    const int NK = HID / 128;  // 8
    for (int ko = 0; ko < NK; ko++) {
        CP_WAIT(1);
        __syncthreads();
        if (ko + 2 < NK) issue((ko + 2) % 3, (ko + 2) * 128);
        CP_COMMIT();
        uint32_t sa = sbase + (uint32_t)(ko % 3) * STAGE_B;
        compute32x64_f8<4>(c, sa, sa + HTILE_B, wm, wn, lane);
    }
    CP_WAIT(0);
    __syncthreads();

    // stage tg*(c+bd) fp32 (stride 132 floats = 528B, 16B-aligned), coalesced epilogue
    const float tg = tanhf(gate[0]);
    float* sEpF = (float*)dyn;
    const int g = lane >> 2, t4 = lane & 3;
    #pragma unroll
    for (int mi = 0; mi < 2; mi++) {
        int r0 = wm * 32 + mi * 16 + g;
        #pragma unroll
        for (int nj = 0; nj < 8; nj++) {
            int cc = wn * 64 + nj * 8 + t4 * 2;
            float2 b2 = *(const float2*)&bd[n0 + cc];
            sEpF[r0 * 132 + cc]           = tg * (c[mi][nj][0] + b2.x);
            sEpF[r0 * 132 + cc + 1]       = tg * (c[mi][nj][1] + b2.y);
            sEpF[(r0 + 8) * 132 + cc]     = tg * (c[mi][nj][2] + b2.x);
            sEpF[(r0 + 8) * 132 + cc + 1] = tg * (c[mi][nj][3] + b2.y);
        }
    }
    __syncthreads();
    #pragma unroll
    for (int u = 0; u < 16; u++) {
        int idx = u * 256 + tid, r = idx >> 5, cc = (idx & 31) * 4;
        size_t go = (size_t)(m0 + r) * DIMD + n0 + cc;
        float4 d = *(float4*)&sEpF[r * 132 + cc];
        uint2 h2 = *(const uint2*)&g_x0b[go];
        uint2 l2 = *(const uint2*)&g_x0lo[go];
        float2 ha = __bfloat1622float2(*(__nv_bfloat162*)&h2.x);
        float2 hb = __bfloat1622float2(*(__nv_bfloat162*)&h2.y);
        float2 la = __bfloat1622float2(*(__nv_bfloat162*)&l2.x);
        float2 lb = __bfloat1622float2(*(__nv_bfloat162*)&l2.y);
        float y0 = ha.x + la.x + d.x;
        float y1 = ha.y + la.y + d.y;
        float y2 = hb.x + lb.x + d.z;
        float y3 = hb.y + lb.y + d.w;
        __nv_bfloat16 oh[4], ol[4];
        hilo(y0, oh[0], ol[0]); hilo(y1, oh[1], ol[1]);
        hilo(y2, oh[2], ol[2]); hilo(y3, oh[3], ol[3]);
        *(uint2*)&g_x1b[go]  = *(uint2*)oh;
        *(uint2*)&g_x1lo[go] = *(uint2*)ol;
    }
}

// ================= G3: VQ argmin (flat 32-iter pipeline) + fused epilogue =================
__global__ void __launch_bounds__(256, 2) g3_kernel(const float* __restrict__ mb,
                                                    float* __restrict__ out)
{
    extern __shared__ char dyn3[];
    const uint32_t sbase = smem_u32(dyn3);
    float* scn = (float*)(dyn3 + G12_DS);
    const int tid = threadIdx.x, lane = tid & 31, wid = tid >> 5;
    const int wm = wid & 3, wn = wid >> 2;
    const int m0 = blockIdx.x << 7;

    for (int i = tid; i < NMEM; i += 256) scn[i] = g_cnorm[i];

    float bestv[4] = {3.4e38f, 3.4e38f, 3.4e38f, 3.4e38f};
    int   besti[4] = {0, 0, 0, 0};
    float c[2][8][4];
    #pragma unroll
    for (int i = 0; i < 2; i++)
        #pragma unroll
        for (int j = 0; j < 8; j++)
            #pragma unroll
            for (int q = 0; q < 4; q++) c[i][j][q] = 0.f;

    const int g = lane >> 2, t4 = lane & 3;
    const int rr = tid >> 3, ch = tid & 7;

    auto issue = [&](int it) {
        int stage = it % 3;
        int k0 = (it & 7) << 6;
        int nb0 = (it >> 3) << 7;
        uint32_t sa = sbase + stage * STAGE_B;
        uint32_t sb = sa + HTILE_B;
        #pragma unroll
        for (int u = 0; u < 4; u++) {
            int r = rr + u * 32;
            cp16(sa + (uint32_t)(r * 144 + ch * 16),
                 &g_x1b[(size_t)(m0 + r) * DIMD + k0 + ch * 8]);
            cp16(sb + (uint32_t)(r * 144 + ch * 16),
                 &g_mbb[(size_t)(nb0 + r) * DIMD + k0 + ch * 8]);
        }
    };
    issue(0); CP_COMMIT();
    issue(1); CP_COMMIT();

    for (int it = 0; it < 32; it++) {
        CP_WAIT(1);
        __syncthreads();
        if (it + 2 < 32) issue(it + 2);
        CP_COMMIT();
        uint32_t sa = sbase + (uint32_t)(it % 3) * STAGE_B;
        compute32x64<4>(c, sa, sa + HTILE_B, 72, 0, wm, wn, lane);
        if ((it & 7) == 7) {
            int nb0 = (it >> 3) << 7;
            #pragma unroll
            for (int mi = 0; mi < 2; mi++)
                #pragma unroll
                for (int rj = 0; rj < 2; rj++) {
                    int slot = mi * 2 + rj;
                    #pragma unroll
                    for (int nj = 0; nj < 8; nj++)
                        #pragma unroll
                        for (int jc = 0; jc < 2; jc++) {
                            int col = nb0 + wn * 64 + nj * 8 + t4 * 2 + jc;
                            float sc = fmaf(-2.f, c[mi][nj][rj * 2 + jc], scn[col]);
                            if (sc < bestv[slot]) { bestv[slot] = sc; besti[slot] = col; }
                        }
                }
            #pragma unroll
            for (int i = 0; i < 2; i++)
                #pragma unroll
                for (int j = 0; j < 8; j++)
                    #pragma unroll
                    for (int q = 0; q < 4; q++) c[i][j][q] = 0.f;
        }
    }
    CP_WAIT(0);
    __syncthreads();

    float* sVal = (float*)dyn3;
    int*   sI2  = (int*)(dyn3 + 1024);
    int*   sIdx = (int*)(dyn3 + 2048);

    #pragma unroll
    for (int slot = 0; slot < 4; slot++) {
        float v = bestv[slot]; int ix = besti[slot];
        #pragma unroll
        for (int o = 1; o <= 2; o <<= 1) {
            float ov = __shfl_xor_sync(0xffffffffu, v, o);
            int   oi = __shfl_xor_sync(0xffffffffu, ix, o);
            if (ov < v || (ov == v && oi < ix)) { v = ov; ix = oi; }
        }
        bestv[slot] = v; besti[slot] = ix;
    }
    if (t4 == 0) {
        #pragma unroll
        for (int mi = 0; mi < 2; mi++)
            #pragma unroll
            for (int rj = 0; rj < 2; rj++) {
                int rl = wm * 32 + mi * 16 + g + rj * 8;
                sVal[wn * 128 + rl] = bestv[mi * 2 + rj];
                sI2[wn * 128 + rl]  = besti[mi * 2 + rj];
            }
    }
    __syncthreads();
    if (tid < 128) {
        float v0 = sVal[tid], v1 = sVal[128 + tid];
        int i0 = sI2[tid], i1 = sI2[128 + tid];
        sIdx[tid] = (v1 < v0 || (v1 == v0 && i1 < i0)) ? i1 : i0;
    }
    __syncthreads();

    for (int it = 0; it < 16; it++) {
        int rl = it * 8 + wid;
        int idx = sIdx[rl];
        size_t rbase = (size_t)(m0 + rl) * DIMD;
        size_t cbase = (size_t)idx * DIMD;
        float ss = 0.f;
        float4 vv[4];
        #pragma unroll
        for (int j = 0; j < 4; j++) {
            int col = j * 128 + lane * 4;
            uint2 h2 = *(const uint2*)&g_x1b[rbase + col];
            uint2 l2 = *(const uint2*)&g_x1lo[rbase + col];
            float4 cd = *(const float4*)&mb[cbase + col];
            float2 ha = __bfloat1622float2(*(__nv_bfloat162*)&h2.x);
            float2 hb = __bfloat1622float2(*(__nv_bfloat162*)&h2.y);
            float2 la = __bfloat1622float2(*(__nv_bfloat162*)&l2.x);
            float2 lb = __bfloat1622float2(*(__nv_bfloat162*)&l2.y);
            float a0 = fixv(ha.x + la.x + 0.05f * cd.x);
            float a1 = fixv(ha.y + la.y + 0.05f * cd.y);
            float a2 = fixv(hb.x + lb.x + 0.05f * cd.z);
            float a3 = fixv(hb.y + lb.y + 0.05f * cd.w);
            vv[j] = make_float4(a0, a1, a2, a3);
            ss += a0 * a0 + a1 * a1 + a2 * a2 + a3 * a3;
        }
        #pragma unroll
        for (int o = 16; o > 0; o >>= 1) ss += __shfl_xor_sync(0xffffffffu, ss, o);
        float nrm = sqrtf(ss);
        float scale = (nrm > 10.f) ? (10.f / fmaxf(nrm, 1e-6f)) : 1.f;
        #pragma unroll
        for (int j = 0; j < 4; j++) {
            int col = j * 128 + lane * 4;
            *(float4*)&out[rbase + col] =
                make_float4(vv[j].x * scale, vv[j].y * scale, vv[j].z * scale, vv[j].w * scale);
        }
    }
}

// ---------------- launch ----------------
extern "C" void kernel_launch(void* const* d_in, const int* in_sizes, int n_in,
                              void* d_out, int out_size) {
    const float* ie   = (const float*)d_in[0];
    const float* nb   = (const float*)d_in[1];
    const float* mu   = (const float*)d_in[2];
    const float* wu   = (const float*)d_in[3];
    const float* bu   = (const float*)d_in[4];
    const float* wd   = (const float*)d_in[5];
    const float* bd   = (const float*)d_in[6];
    const float* gate = (const float*)d_in[7];
    const float* mb   = (const float*)d_in[8];
    float* out = (float*)d_out;

    cudaFuncSetAttribute(g1_kernel, cudaFuncAttributeMaxDynamicSharedMemorySize, G12_DS);
    cudaFuncSetAttribute(g2_kernel, cudaFuncAttributeMaxDynamicSharedMemorySize, G12_DS);
    cudaFuncSetAttribute(g3_kernel, cudaFuncAttributeMaxDynamicSharedMemorySize, G3_DS);

    kpre<<<37952, 256>>>(ie, nb, mu, wu, wd, mb);
    g1_kernel<<<dim3(HID / 128, NROWS / 128), 256, G12_DS>>>(bu);
    g2_kernel<<<dim3(DIMD / 128, NROWS / 128), 256, G12_DS>>>(bd, gate);
    g3_kernel<<<NROWS / 128, 256, G3_DS>>>(mb, out);
}